// round 6
// baseline (speedup 1.0000x reference)
#include <cuda_runtime.h>
#include <cstddef>

// ---------------- problem constants ----------------
#define B_   32
#define T_   128
#define P_   4
#define DIN_ 512
#define H_   512
#define C_   4096
#define G_   16384
#define NB   128
#define NT   512

// ---------------- device scratch ----------------
__device__ float g_pi [(size_t)B_ * T_ * G_];   // [b*T+t][j]        268 MB
__device__ float g_mem[(size_t)T_ * C_ * B_];   // [t][c][b]          67 MB
__device__ float g_st [(size_t)T_ * H_ * B_];   // [t][h][b]         8.4 MB
__device__ float g_a  [C_ * B_];                // [c][b]
__device__ float g_pst[H_ * B_];                // [k][b]
__device__ unsigned g_bar_count;
__device__ volatile unsigned g_bar_sense;

// ---------------- f32x2 helpers ----------------
__device__ __forceinline__ unsigned long long pack2(float a, float b) {
    unsigned long long d;
    unsigned x = __float_as_uint(a), y = __float_as_uint(b);
    asm("mov.b64 %0, {%1,%2};" : "=l"(d) : "r"(x), "r"(y));
    return d;
}
__device__ __forceinline__ unsigned long long dup2(float a) { return pack2(a, a); }
__device__ __forceinline__ void unpack2(unsigned long long s, float& a, float& b) {
    unsigned x, y;
    asm("mov.b64 {%0,%1}, %2;" : "=r"(x), "=r"(y) : "l"(s));
    a = __uint_as_float(x); b = __uint_as_float(y);
}
__device__ __forceinline__ unsigned long long fma2(unsigned long long a,
                                                   unsigned long long b,
                                                   unsigned long long c) {
    unsigned long long d;
    asm("fma.rn.f32x2 %0, %1, %2, %3;" : "=l"(d) : "l"(a), "l"(b), "l"(c));
    return d;
}
__device__ __forceinline__ float sigmoidf(float x) { return 1.0f / (1.0f + __expf(-x)); }

// ---------------- grid barrier ----------------
__device__ __forceinline__ void grid_barrier(unsigned& sense) {
    __syncthreads();
    if (threadIdx.x == 0) {
        unsigned s = sense ^ 1u;
        sense = s;
        __threadfence();
        unsigned old = atomicAdd(&g_bar_count, 1u);
        if (old == (unsigned)(gridDim.x - 1)) {
            g_bar_count = 0;
            __threadfence();
            g_bar_sense = s;
        } else {
            while (g_bar_sense != s) { __nanosleep(32); }
        }
        __threadfence();
    }
    __syncthreads();
}

// =====================================================================
// Kernel 1: proj_in = x @ W_in^T  -> g_pi[(b*T+t)*G + j]
// =====================================================================
__global__ void __launch_bounds__(256) proj_in_kernel(const float* __restrict__ x,
                                                      const float* __restrict__ W_in) {
    __shared__ __align__(16) float As[16][128];
    __shared__ __align__(16) float Bs[16][128];

    const int tid = threadIdx.x;
    const int m0 = blockIdx.y * 128;
    const int n0 = blockIdx.x * 128;
    const int tm = tid >> 4;
    const int tn = tid & 15;

    unsigned long long acc[8][4];
#pragma unroll
    for (int i = 0; i < 8; i++)
#pragma unroll
        for (int j = 0; j < 4; j++) acc[i][j] = 0ull;

    for (int kk = 0; kk < DIN_; kk += 16) {
#pragma unroll
        for (int r = 0; r < 2; r++) {
            int f = tid + r * 256;
            int row = f >> 2;
            int kq = f & 3;
            float4 va = *(const float4*)&x[(size_t)(m0 + row) * DIN_ + kk + kq * 4];
            As[kq * 4 + 0][row] = va.x; As[kq * 4 + 1][row] = va.y;
            As[kq * 4 + 2][row] = va.z; As[kq * 4 + 3][row] = va.w;
            float4 vb = *(const float4*)&W_in[(size_t)(n0 + row) * DIN_ + kk + kq * 4];
            Bs[kq * 4 + 0][row] = vb.x; Bs[kq * 4 + 1][row] = vb.y;
            Bs[kq * 4 + 2][row] = vb.z; Bs[kq * 4 + 3][row] = vb.w;
        }
        __syncthreads();
#pragma unroll
        for (int k = 0; k < 16; k++) {
            float4 a0 = *(const float4*)&As[k][tm * 8];
            float4 a1 = *(const float4*)&As[k][tm * 8 + 4];
            ulonglong2 b0 = *(const ulonglong2*)&Bs[k][tn * 8];
            ulonglong2 b1 = *(const ulonglong2*)&Bs[k][tn * 8 + 4];
            float av[8] = {a0.x, a0.y, a0.z, a0.w, a1.x, a1.y, a1.z, a1.w};
#pragma unroll
            for (int i = 0; i < 8; i++) {
                unsigned long long pa = dup2(av[i]);
                acc[i][0] = fma2(pa, b0.x, acc[i][0]);
                acc[i][1] = fma2(pa, b0.y, acc[i][1]);
                acc[i][2] = fma2(pa, b1.x, acc[i][2]);
                acc[i][3] = fma2(pa, b1.y, acc[i][3]);
            }
        }
        __syncthreads();
    }
#pragma unroll
    for (int i = 0; i < 8; i++) {
        float o[8];
        unpack2(acc[i][0], o[0], o[1]); unpack2(acc[i][1], o[2], o[3]);
        unpack2(acc[i][2], o[4], o[5]); unpack2(acc[i][3], o[6], o[7]);
        size_t base = (size_t)(m0 + tm * 8 + i) * G_ + n0 + tn * 8;
        *(float4*)&g_pi[base]     = make_float4(o[0], o[1], o[2], o[3]);
        *(float4*)&g_pi[base + 4] = make_float4(o[4], o[5], o[6], o[7]);
    }
}

// =====================================================================
// Kernel 2: persistent scan. 128 blocks x 512 threads, lane = batch.
// =====================================================================
__global__ void __launch_bounds__(NT, 1) scan_kernel(
    const int*   __restrict__ prev_idx,
    const float* __restrict__ prev_w,
    const float* __restrict__ W_state,
    const float* __restrict__ b_state,
    const float* __restrict__ W_proj,
    float* __restrict__ out)
{
    extern __shared__ __align__(16) float sm[];
    float*  sWp   = sm;                       // [c][h0..3]    16384 f (persistent)
    float*  s_pst = sm + 16384;               // [k][b]        16384 f (alias s_a)
    float2* sW2   = (float2*)(sm + 32768);    // [kp][j]        8192 f
    float*  part  = sm + 32768;               // alias (B reduce) 2048 f

    const int tid = threadIdx.x;
    const int bid = blockIdx.x;
    const int w   = tid >> 5;   // warp 0..15
    const int b   = tid & 31;   // lane = batch
    unsigned sense = 0;

    // ---- stage W_proj rows [bid*4 .. bid*4+3] once, layout sWp[c*4+h] ----
    {
        const int h0 = bid * 4;
        for (int e = tid; e < 4 * C_; e += NT) {
            int h = e >> 12;
            int c = e & (C_ - 1);
            sWp[c * 4 + h] = __ldg(&W_proj[(size_t)(h0 + h) * C_ + c]);
        }
    }

    // per-thread constants (c-tile: c = bid*32 + 2w + ci)
    const int cA0 = bid * 32 + 2 * w;
    float bst[2][4];
#pragma unroll
    for (int ci = 0; ci < 2; ci++)
#pragma unroll
        for (int g = 0; g < 4; g++)
            bst[ci][g] = __ldg(&b_state[g * C_ + cA0 + ci]);

    for (int t = 0; t < T_; t++) {
        // ================= Phase A =================
        int   idxA[P_];
        float wA[P_];
#pragma unroll
        for (int p = 0; p < P_; p++) {
            idxA[p] = __ldg(&prev_idx[(b * T_ + t) * P_ + p]);
            wA[p]   = __ldg(&prev_w [(b * T_ + t) * P_ + p]);
        }
        float piv[2][4], pmv[2][P_];
#pragma unroll
        for (int ci = 0; ci < 2; ci++) {
            const int c = cA0 + ci;
#pragma unroll
            for (int g = 0; g < 4; g++)
                piv[ci][g] = __ldg(&g_pi[(size_t)(b * T_ + t) * G_ + g * C_ + c]);
#pragma unroll
            for (int p = 0; p < P_; p++)
                pmv[ci][p] = g_mem[((size_t)idxA[p] * C_ + c) * B_ + b];
        }

        unsigned long long acc[8];
#pragma unroll
        for (int i = 0; i < 8; i++) acc[i] = 0ull;

        if (t > 0) {
            // stage pooled state [k][b]
            for (int i = tid; i < (H_ * B_) / 4; i += NT)
                ((float4*)s_pst)[i] = __ldcg(((const float4*)g_pst) + i);

            for (int kk = 0; kk < H_; kk += 64) {
                // stage W_state chunk: sW2[kp*128 + j], j = c_l*4 + g
#pragma unroll
                for (int i = 0; i < 4; i++) {
                    int e = tid + i * NT;           // 0..2047
                    int j = e & 127;
                    int q = e >> 7;                 // 0..15
                    int jglob = (j & 3) * C_ + bid * 32 + (j >> 2);
                    float4 v = __ldg((const float4*)&W_state[(size_t)jglob * H_ + kk + q * 4]);
                    sW2[(q * 2    ) * 128 + j] = make_float2(v.x, v.y);
                    sW2[(q * 2 + 1) * 128 + j] = make_float2(v.z, v.w);
                }
                __syncthreads();
#pragma unroll
                for (int kp = 0; kp < 32; kp++) {
                    const int k = kk + 2 * kp;
                    unsigned long long pa = pack2(s_pst[k * 32 + b], s_pst[(k + 1) * 32 + b]);
                    const ulonglong2* wp = (const ulonglong2*)&sW2[kp * 128 + w * 8];
                    ulonglong2 q0 = wp[0], q1 = wp[1], q2 = wp[2], q3 = wp[3];
                    acc[0] = fma2(q0.x, pa, acc[0]); acc[1] = fma2(q0.y, pa, acc[1]);
                    acc[2] = fma2(q1.x, pa, acc[2]); acc[3] = fma2(q1.y, pa, acc[3]);
                    acc[4] = fma2(q2.x, pa, acc[4]); acc[5] = fma2(q2.y, pa, acc[5]);
                    acc[6] = fma2(q3.x, pa, acc[6]); acc[7] = fma2(q3.y, pa, acc[7]);
                }
                __syncthreads();
            }
        }

        // epilogue: gates + mem update + a
#pragma unroll
        for (int ci = 0; ci < 2; ci++) {
            const int c = cA0 + ci;
            float pmem = 0.f;
#pragma unroll
            for (int p = 0; p < P_; p++) pmem += wA[p] * pmv[ci][p];
            float gv[4];
#pragma unroll
            for (int g = 0; g < 4; g++) {
                float lo, hi;
                unpack2(acc[4 * ci + g], lo, hi);
                gv[g] = lo + hi + piv[ci][g] + bst[ci][g];
            }
            float ig = sigmoidf(gv[0]);
            float fg = sigmoidf(gv[1]);
            float mi = tanhf(gv[2]);
            float og = sigmoidf(gv[3]);
            float mem = fminf(3.f, fmaxf(-3.f, ig * mi + fg * pmem));
            g_mem[((size_t)t * C_ + c) * B_ + b] = mem;
            __stcg(&g_a[c * B_ + b], og * tanhf(mem));
        }
        grid_barrier(sense);

        // ================= Phase B: projection (4 h rows, full K) =================
        unsigned long long pacc0 = 0ull, pacc1 = 0ull;
        float* s_a = s_pst;
        for (int ch = 0; ch < 8; ch++) {
            const int cc = ch * 512;
            for (int i = tid; i < (512 * 32) / 4; i += NT)
                ((float4*)s_a)[i] = __ldcg((const float4*)g_a + ch * 4096 + i);
            __syncthreads();
#pragma unroll
            for (int k = 0; k < 32; k++) {
                const int cl = w * 32 + k;
                unsigned long long pa = dup2(s_a[cl * 32 + b]);
                ulonglong2 q = *(const ulonglong2*)&sWp[(cc + cl) * 4];
                pacc0 = fma2(q.x, pa, pacc0);
                pacc1 = fma2(q.y, pa, pacc1);
            }
            __syncthreads();
        }
        {
            float v0, v1, v2, v3;
            unpack2(pacc0, v0, v1);
            unpack2(pacc1, v2, v3);
            part[(w * 4 + 0) * 32 + b] = v0;
            part[(w * 4 + 1) * 32 + b] = v1;
            part[(w * 4 + 2) * 32 + b] = v2;
            part[(w * 4 + 3) * 32 + b] = v3;
        }
        __syncthreads();
        if (tid < 128) {
            const int hl = tid >> 5;
            const int bb = tid & 31;
            float s = 0.f;
#pragma unroll
            for (int ww = 0; ww < 16; ww++) s += part[(ww * 4 + hl) * 32 + bb];
            s = fminf(3.f, fmaxf(-3.f, s));
            const int hg = bid * 4 + hl;
            g_st[((size_t)t * H_ + hg) * B_ + bb] = s;
            out[((size_t)bb * T_ + t) * H_ + hg] = s;
            if (t < T_ - 1) {
                float pstv = 0.f;
#pragma unroll
                for (int p = 0; p < P_; p++) {
                    int ip   = __ldg(&prev_idx[(bb * T_ + t + 1) * P_ + p]);
                    float wv = __ldg(&prev_w [(bb * T_ + t + 1) * P_ + p]);
                    float v  = (ip == t) ? s : g_st[((size_t)ip * H_ + hg) * B_ + bb];
                    pstv += wv * v;
                }
                __stcg(&g_pst[hg * B_ + bb], pstv);
            }
        }
        grid_barrier(sense);
    }
}

// =====================================================================
// launch
// =====================================================================
extern "C" void kernel_launch(void* const* d_in, const int* in_sizes, int n_in,
                              void* d_out, int out_size) {
    const float* x        = (const float*)d_in[0];
    const int*   prev_idx = (const int*)  d_in[1];
    const float* prev_w   = (const float*)d_in[2];
    const float* W_in     = (const float*)d_in[3];
    const float* W_state  = (const float*)d_in[4];
    const float* b_state  = (const float*)d_in[5];
    const float* W_proj   = (const float*)d_in[6];
    float* out = (float*)d_out;
    (void)in_sizes; (void)n_in; (void)out_size;

    const int smem = (16384 + 16384 + 8192) * (int)sizeof(float);   // 160 KB
    cudaFuncSetAttribute(scan_kernel, cudaFuncAttributeMaxDynamicSharedMemorySize, smem);

    proj_in_kernel<<<dim3(G_ / 128, (B_ * T_) / 128), 256>>>(x, W_in);
    scan_kernel<<<NB, NT, smem>>>(prev_idx, prev_w, W_state, b_state, W_proj, out);
}

// round 8
// speedup vs baseline: 1.1426x; 1.1426x over previous
#include <cuda_runtime.h>
#include <cstddef>

#define B_   32
#define T_   128
#define P_   4
#define DIN_ 512
#define H_   512
#define C_   4096
#define G_   16384
#define NBLK 128
#define NT   512

typedef unsigned long long ull;

__device__ float g_pi  [(size_t)B_ * T_ * G_];
__device__ float g_mem [(size_t)T_ * C_ * B_];
__device__ float g_st  [(size_t)T_ * H_ * B_];
__device__ float g_a2  [C_ * B_];
__device__ float g_pst2[H_ * B_];
__device__ float g_hp  [NBLK * 1024];
__device__ int   g_cntA[T_ * 8];
__device__ int   g_cntB[T_ * 16];
__device__ int   g_done[T_];

__device__ __forceinline__ ull pack2(float a, float b) {
    ull d;
    unsigned x = __float_as_uint(a), y = __float_as_uint(b);
    asm("mov.b64 %0, {%1,%2};" : "=l"(d) : "r"(x), "r"(y));
    return d;
}
__device__ __forceinline__ ull dup2(float a) { return pack2(a, a); }
__device__ __forceinline__ void unpack2(ull s, float& a, float& b) {
    unsigned x, y;
    asm("mov.b64 {%0,%1}, %2;" : "=r"(x), "=r"(y) : "l"(s));
    a = __uint_as_float(x); b = __uint_as_float(y);
}
__device__ __forceinline__ ull fma2(ull a, ull b, ull c) {
    ull d;
    asm("fma.rn.f32x2 %0, %1, %2, %3;" : "=l"(d) : "l"(a), "l"(b), "l"(c));
    return d;
}
__device__ __forceinline__ float sigmoidf(float x) { return 1.0f / (1.0f + __expf(-x)); }

__device__ __forceinline__ int ld_acq(const int* p) {
    int v;
    asm volatile("ld.acquire.gpu.global.b32 %0, [%1];" : "=r"(v) : "l"(p) : "memory");
    return v;
}
__device__ __forceinline__ int atom_add_acqrel(int* p, int v) {
    int old;
    asm volatile("atom.acq_rel.gpu.global.add.s32 %0, [%1], %2;"
                 : "=r"(old) : "l"(p), "r"(v) : "memory");
    return old;
}
__device__ __forceinline__ void cp16(float* s, const float* g) {
    unsigned sa = (unsigned)__cvta_generic_to_shared(s);
    asm volatile("cp.async.cg.shared.global [%0], [%1], 16;" :: "r"(sa), "l"(g));
}
#define CP_COMMIT() asm volatile("cp.async.commit_group;")
#define CP_WAIT0()  asm volatile("cp.async.wait_group 0;")

__global__ void init_sig() {
    int i = blockIdx.x * blockDim.x + threadIdx.x;
    if (i < T_ * 8)  g_cntA[i] = 0;
    if (i < T_ * 16) g_cntB[i] = 0;
    if (i < T_)      g_done[i] = 0;
}

__global__ void __launch_bounds__(256) proj_in_kernel(const float* __restrict__ x,
                                                      const float* __restrict__ W_in) {
    __shared__ __align__(16) float As[16][128];
    __shared__ __align__(16) float Bs[16][128];
    const int tid = threadIdx.x;
    const int m0 = blockIdx.y * 128;
    const int n0 = blockIdx.x * 128;
    const int tm = tid >> 4;
    const int tn = tid & 15;

    ull acc[8][4];
#pragma unroll
    for (int i = 0; i < 8; i++)
#pragma unroll
        for (int j = 0; j < 4; j++) acc[i][j] = 0ull;

    for (int kk = 0; kk < DIN_; kk += 16) {
#pragma unroll
        for (int r = 0; r < 2; r++) {
            int f = tid + r * 256;
            int row = f >> 2;
            int kq = f & 3;
            float4 va = *(const float4*)&x[(size_t)(m0 + row) * DIN_ + kk + kq * 4];
            As[kq * 4 + 0][row] = va.x; As[kq * 4 + 1][row] = va.y;
            As[kq * 4 + 2][row] = va.z; As[kq * 4 + 3][row] = va.w;
            float4 vb = *(const float4*)&W_in[(size_t)(n0 + row) * DIN_ + kk + kq * 4];
            Bs[kq * 4 + 0][row] = vb.x; Bs[kq * 4 + 1][row] = vb.y;
            Bs[kq * 4 + 2][row] = vb.z; Bs[kq * 4 + 3][row] = vb.w;
        }
        __syncthreads();
#pragma unroll
        for (int k = 0; k < 16; k++) {
            float4 a0 = *(const float4*)&As[k][tm * 8];
            float4 a1 = *(const float4*)&As[k][tm * 8 + 4];
            ulonglong2 b0 = *(const ulonglong2*)&Bs[k][tn * 8];
            ulonglong2 b1 = *(const ulonglong2*)&Bs[k][tn * 8 + 4];
            float av[8] = {a0.x, a0.y, a0.z, a0.w, a1.x, a1.y, a1.z, a1.w};
#pragma unroll
            for (int i = 0; i < 8; i++) {
                ull pa = dup2(av[i]);
                acc[i][0] = fma2(pa, b0.x, acc[i][0]);
                acc[i][1] = fma2(pa, b0.y, acc[i][1]);
                acc[i][2] = fma2(pa, b1.x, acc[i][2]);
                acc[i][3] = fma2(pa, b1.y, acc[i][3]);
            }
        }
        __syncthreads();
    }
#pragma unroll
    for (int i = 0; i < 8; i++) {
        float o[8];
        unpack2(acc[i][0], o[0], o[1]); unpack2(acc[i][1], o[2], o[3]);
        unpack2(acc[i][2], o[4], o[5]); unpack2(acc[i][3], o[6], o[7]);
        size_t base = (size_t)(m0 + tm * 8 + i) * G_ + n0 + tn * 8;
        *(float4*)&g_pi[base]     = make_float4(o[0], o[1], o[2], o[3]);
        *(float4*)&g_pi[base + 4] = make_float4(o[4], o[5], o[6], o[7]);
    }
}

#define SMEM_FLOATS 54664

__device__ __forceinline__ void ldg_chunkW(float2* wreg, const float* __restrict__ W_state,
                                           int bid, int tid, int ch) {
#pragma unroll
    for (int r = 0; r < 8; r++) {
        int e  = r * NT + tid;
        int j  = e >> 5;
        int kp = e & 31;
        int jg = (j & 3) * C_ + bid * 32 + (j >> 2);
        wreg[r] = __ldg((const float2*)&W_state[(size_t)jg * H_ + ch * 64 + kp * 2]);
    }
}
__device__ __forceinline__ void sts_chunkW(float* buf, const float2* wreg, int tid) {
#pragma unroll
    for (int r = 0; r < 8; r++) {
        int e  = r * NT + tid;
        int j  = e >> 5;
        int kp = e & 31;
        ((float2*)buf)[kp * 130 + j] = wreg[r];
    }
}

__global__ void __launch_bounds__(NT, 1) scan_kernel(
    const int*   __restrict__ prev_idx,
    const float* __restrict__ prev_w,
    const float* __restrict__ W_state,
    const float* __restrict__ b_state,
    const float* __restrict__ W_proj,
    float* __restrict__ out)
{
    extern __shared__ __align__(16) float sm[];
    float* s_big  = sm;
    float* sW0    = sm + 16384;
    float* sW1    = sm + 24704;
    float* s_pi   = sm + 33024;
    int*   s_flag = (int*)(sm + 37248);
    float* sWpB   = sm + 37256;

    const int tid = threadIdx.x;
    const int bid = blockIdx.x;
    const int w   = tid >> 5;
    const int b   = tid & 31;
    const int ht  = bid >> 3;
    const int ks  = bid & 7;
    const int ksA = bid >> 4;

    for (int r = 0; r < 32; r++) {
        int e  = r * NT + tid;
        int hl = e >> 9;
        int c  = e & 511;
        sWpB[c * 34 + hl] = __ldg(&W_proj[(size_t)(ht * 32 + hl) * C_ + ks * 512 + c]);
    }
    const int cA = bid * 32 + w * 2;
    float bst[2][4];
#pragma unroll
    for (int ci = 0; ci < 2; ci++)
#pragma unroll
        for (int g = 0; g < 4; g++)
            bst[ci][g] = __ldg(&b_state[g * C_ + cA + ci]);
    __syncthreads();

    for (int t = 0; t < T_; t++) {
        int idxA[P_]; float wA[P_];
#pragma unroll
        for (int p = 0; p < P_; p++) {
            idxA[p] = __ldg(&prev_idx[(b * T_ + t) * P_ + p]);
            wA[p]   = __ldg(&prev_w [(b * T_ + t) * P_ + p]);
        }
        float pmv[2][P_];
#pragma unroll
        for (int ci = 0; ci < 2; ci++)
#pragma unroll
            for (int p = 0; p < P_; p++)
                pmv[ci][p] = g_mem[((size_t)idxA[p] * C_ + cA + ci) * B_ + b];
#pragma unroll
        for (int r = 0; r < 8; r++) {
            int e  = r * NT + tid;
            int bb = e >> 7;
            int gg = (e >> 5) & 3;
            int cl = e & 31;
            s_pi[(gg * 32 + cl) * 33 + bb] =
                __ldg(&g_pi[((size_t)(bb * T_ + t)) * G_ + gg * C_ + bid * 32 + cl]);
        }
        // Order s_pi staging before epilogue reads. Mandatory for t==0 (GEMM
        // branch skipped => no other barrier between staging and consumption).
        __syncthreads();

        ull acc[8];
#pragma unroll
        for (int i = 0; i < 8; i++) acc[i] = 0ull;

        if (t > 0) {
            float2 wreg[8];
            ldg_chunkW(wreg, W_state, bid, tid, 0);
            if (tid == 0) { while (ld_acq(&g_done[t - 1]) != 16) __nanosleep(40); }
            __syncthreads();
#pragma unroll
            for (int r = 0; r < 8; r++) {
                int e = r * NT + tid;
                cp16(s_big + e * 4, g_pst2 + e * 4);
            }
            CP_COMMIT();
            sts_chunkW(sW0, wreg, tid);
            CP_WAIT0();
            __syncthreads();

#pragma unroll 1
            for (int ch = 0; ch < 8; ch++) {
                float* buf  = (ch & 1) ? sW1 : sW0;
                float* nbuf = (ch & 1) ? sW0 : sW1;
                if (ch < 7) ldg_chunkW(wreg, W_state, bid, tid, ch + 1);
#pragma unroll
                for (int kp = 0; kp < 32; kp++) {
                    ull pa = *(const ull*)(s_big + ((ch * 32 + kp) * 64 + b * 2));
                    const ulonglong2* wp = (const ulonglong2*)(buf + (kp * 130 + w * 8) * 2);
                    ulonglong2 q0 = wp[0], q1 = wp[1], q2 = wp[2], q3 = wp[3];
                    acc[0] = fma2(q0.x, pa, acc[0]); acc[1] = fma2(q0.y, pa, acc[1]);
                    acc[2] = fma2(q1.x, pa, acc[2]); acc[3] = fma2(q1.y, pa, acc[3]);
                    acc[4] = fma2(q2.x, pa, acc[4]); acc[5] = fma2(q2.y, pa, acc[5]);
                    acc[6] = fma2(q3.x, pa, acc[6]); acc[7] = fma2(q3.y, pa, acc[7]);
                }
                __syncthreads();
                if (ch < 7) sts_chunkW(nbuf, wreg, tid);
                __syncthreads();
            }
        }
        {
            float a2v[2];
#pragma unroll
            for (int ci = 0; ci < 2; ci++) {
                float pmem = 0.f;
#pragma unroll
                for (int p = 0; p < P_; p++) pmem += wA[p] * pmv[ci][p];
                float gv[4];
#pragma unroll
                for (int g = 0; g < 4; g++) {
                    float lo, hi;
                    unpack2(acc[ci * 4 + g], lo, hi);
                    gv[g] = lo + hi + s_pi[(g * 32 + w * 2 + ci) * 33 + b] + bst[ci][g];
                }
                float ig = sigmoidf(gv[0]);
                float fg = sigmoidf(gv[1]);
                float mi = tanhf(gv[2]);
                float og = sigmoidf(gv[3]);
                float mem = fminf(3.f, fmaxf(-3.f, ig * mi + fg * pmem));
                g_mem[((size_t)t * C_ + cA + ci) * B_ + b] = mem;
                a2v[ci] = og * tanhf(mem);
            }
            *(float2*)&g_a2[(bid * 16 + w) * 64 + b * 2] = make_float2(a2v[0], a2v[1]);
        }
        __syncthreads();
        if (tid == 0) atom_add_acqrel(&g_cntA[t * 8 + ksA], 1);

        if (tid == 0) { while (ld_acq(&g_cntA[t * 8 + ks]) != 16) __nanosleep(32); }
        __syncthreads();
#pragma unroll
        for (int r = 0; r < 8; r++) {
            int e = r * NT + tid;
            cp16(s_big + e * 4, g_a2 + ks * 16384 + e * 4);
        }
        CP_COMMIT();
        CP_WAIT0();
        __syncthreads();

        ull pac[8];
#pragma unroll
        for (int i = 0; i < 8; i++) pac[i] = 0ull;
        const int hhalf = w & 1;
        const int cch   = w >> 1;
#pragma unroll 4
        for (int cp = 0; cp < 32; cp++) {
            int cl2 = cch * 32 + cp;
            ull av = *(const ull*)(s_big + cl2 * 64 + b * 2);
            float alo, ahi;
            unpack2(av, alo, ahi);
            ull dlo = dup2(alo), dhi = dup2(ahi);
            int c0 = cl2 * 2;
#pragma unroll
            for (int hp = 0; hp < 8; hp++) {
                ull w0 = *(const ull*)(sWpB + c0 * 34 + (hhalf * 8 + hp) * 2);
                ull w1 = *(const ull*)(sWpB + (c0 + 1) * 34 + (hhalf * 8 + hp) * 2);
                pac[hp] = fma2(w0, dlo, pac[hp]);
                pac[hp] = fma2(w1, dhi, pac[hp]);
            }
        }
        __syncthreads();
#pragma unroll
        for (int hp = 0; hp < 8; hp++)
            *(ull*)(s_big + ((w * 8 + hp) * 64 + b * 2)) = pac[hp];
        __syncthreads();
#pragma unroll
        for (int r2 = 0; r2 < 2; r2++) {
            int o  = r2 * NT + tid;
            int hl = o >> 5, bb = o & 31;
            int ph   = hl >> 4;
            int hpin = (hl >> 1) & 7;
            int par  = hl & 1;
            float s = 0.f;
#pragma unroll
            for (int q = 0; q < 8; q++)
                s += s_big[((q * 2 + ph) * 8 + hpin) * 64 + bb * 2 + par];
            g_hp[bid * 1024 + hl * 32 + bb] = s;
        }
        __syncthreads();
        if (tid == 0) s_flag[0] = atom_add_acqrel(&g_cntB[t * 16 + ht], 1);
        __syncthreads();

        if (s_flag[0] == 7) {
#pragma unroll
            for (int r2 = 0; r2 < 2; r2++) {
                int o  = r2 * NT + tid;
                int hl = o >> 5, bb = o & 31;
                float s = 0.f;
#pragma unroll
                for (int q = 0; q < 8; q++)
                    s += __ldcg(&g_hp[(ht * 8 + q) * 1024 + hl * 32 + bb]);
                s = fminf(3.f, fmaxf(-3.f, s));
                const int hg = ht * 32 + hl;
                g_st[((size_t)t * H_ + hg) * B_ + bb] = s;
                out[((size_t)bb * T_ + t) * H_ + hg]  = s;
                if (t < T_ - 1) {
                    float pv = 0.f;
#pragma unroll
                    for (int p = 0; p < P_; p++) {
                        int ip   = __ldg(&prev_idx[(bb * T_ + t + 1) * P_ + p]);
                        float wv = __ldg(&prev_w [(bb * T_ + t + 1) * P_ + p]);
                        float v  = (ip == t) ? s : g_st[((size_t)ip * H_ + hg) * B_ + bb];
                        pv += wv * v;
                    }
                    g_pst2[(hg >> 1) * 64 + bb * 2 + (hg & 1)] = pv;
                }
            }
            __syncthreads();
            if (tid == 0) atom_add_acqrel(&g_done[t], 1);
        }
        __syncthreads();
    }
}

extern "C" void kernel_launch(void* const* d_in, const int* in_sizes, int n_in,
                              void* d_out, int out_size) {
    const float* x        = (const float*)d_in[0];
    const int*   prev_idx = (const int*)  d_in[1];
    const float* prev_w   = (const float*)d_in[2];
    const float* W_in     = (const float*)d_in[3];
    const float* W_state  = (const float*)d_in[4];
    const float* b_state  = (const float*)d_in[5];
    const float* W_proj   = (const float*)d_in[6];
    float* out = (float*)d_out;
    (void)in_sizes; (void)n_in; (void)out_size;

    const int smem = SMEM_FLOATS * (int)sizeof(float);
    cudaFuncSetAttribute(scan_kernel, cudaFuncAttributeMaxDynamicSharedMemorySize, smem);

    init_sig<<<2, 1024>>>();
    proj_in_kernel<<<dim3(G_ / 128, (B_ * T_) / 128), 256>>>(x, W_in);
    scan_kernel<<<NBLK, NT, smem>>>(prev_idx, prev_w, W_state, b_state, W_proj, out);
}